// round 13
// baseline (speedup 1.0000x reference)
#include <cuda_runtime.h>
#include <cuda_fp16.h>
#include <cstdint>

#define TOTAL_DIM 24976
#define NQ        97
#define THREADS   256

// ---- dynamic SMEM layout (bytes) ----
#define OFF_BIAS  0
#define OFF_GAMMA 2048
#define OFF_BETA  4096
#define OFF_SSUM  6144     // [32][8] f32
#define OFF_SSSQ  7168     // [32][8] f32
#define OFF_RST   8192     // [32][2] f32
#define OFF_A     8448     // 2 stages x 32 rows x 144B (single fp16 plane)
#define A_STAGE   4608
#define A_ROWB    144
#define OFF_STG   17664    // 16 rows x 520 floats (epilogue store staging, per-mt reuse)
#define STG_PITCH 520
#define SMEM_TOTAL 50944

// ---- prepped weights in MMA FRAGMENT layout ----
// uint4 index: cks*1024 + j*32 + lane   (cks = c*4+ks, j = n16-group 0..31)
__device__ uint4 g_w0[448 * 512 / 8];
__device__ uint4 g_w1[256 * 512 / 8];
__device__ uint4 g_w2[256 * 512 / 8];

__device__ __forceinline__ uint32_t smem_u32(const void* p) {
    uint32_t a;
    asm("{ .reg .u64 t; cvta.to.shared.u64 t, %1; cvt.u32.u64 %0, t; }" : "=r"(a) : "l"(p));
    return a;
}
#define LDSM_X4(r0, r1, r2, r3, a) \
    asm volatile("ldmatrix.sync.aligned.m8n8.x4.shared.b16 {%0,%1,%2,%3}, [%4];" \
                 : "=r"(r0), "=r"(r1), "=r"(r2), "=r"(r3) : "r"(a))
#define MMA16816(c, a0, a1, a2, a3, b0, b1) \
    asm volatile("mma.sync.aligned.m16n8k16.row.col.f32.f16.f16.f32 " \
                 "{%0,%1,%2,%3}, {%4,%5,%6,%7}, {%8,%9}, {%0,%1,%2,%3};" \
                 : "+f"((c)[0]), "+f"((c)[1]), "+f"((c)[2]), "+f"((c)[3]) \
                 : "r"(a0), "r"(a1), "r"(a2), "r"(a3), "r"(b0), "r"(b1))

// ================= fused GEMM + bias + ReLU + LayerNorm =================
// CTA: 32 rows x 512 cols, 8 warps, warp tile 32 x 64 (wn = wid). BK = 64.
// 2 CTAs/SM; B fragments stream from global (L1/L2-hot), A via smem.
// A-ldsm and B-LDG software-pipelined one ks ahead; epilogue stores staged
// through smem for coalesced STG.128.
template <int KSPLIT, int LVALID, int NCHUNK, int SEGOFF, int QOFF>
__device__ __forceinline__ void run_split(const float* __restrict__ x,
                                          const float* __restrict__ bias_g,
                                          const float* __restrict__ gamma_g,
                                          const float* __restrict__ beta_g,
                                          float* __restrict__ out,
                                          const uint4* __restrict__ wfrag,
                                          int tile) {
    extern __shared__ char smem[];
    const uint32_t sb = smem_u32(smem);
    const int tid = threadIdx.x, lane = tid & 31, wn = tid >> 5;
    const int row0 = tile * 32;

    float* bias_s = (float*)(smem + OFF_BIAS);
    float* gam_s  = (float*)(smem + OFF_GAMMA);
    float* bet_s  = (float*)(smem + OFF_BETA);
    for (int i = tid; i < 512; i += THREADS) {
        bias_s[i] = bias_g[i]; gam_s[i] = gamma_g[i]; bet_s[i] = beta_g[i];
    }

    // per-thread x mapping: one row (tid>>3, 0..31), two float4 slots (tid&7, +32 halfs)
    const int xrow = tid >> 3, xf4 = tid & 7;
    const float* px;
    {
        int gr = row0 + xrow;
        int bb = gr / KSPLIT, jj = gr - bb * KSPLIT;
        px = x + (size_t)bb * TOTAL_DIM + SEGOFF + (size_t)jj * LVALID + xf4 * 4;
    }

    float acc[2][8][4];
#pragma unroll
    for (int mt = 0; mt < 2; mt++)
#pragma unroll
        for (int t = 0; t < 8; t++)
#pragma unroll
            for (int c = 0; c < 4; c++) acc[mt][t][c] = 0.f;

    // B fragment base pointer for this warp/lane
    const uint4* bq = wfrag + (size_t)(wn * 4) * 32 + lane;

    float4 xv[2];
#pragma unroll
    for (int sl = 0; sl < 2; sl++) {
        int k0 = xf4 * 4 + sl * 32;
        xv[sl] = (LVALID % 64 == 0 || k0 + 4 <= LVALID) ? *(const float4*)(px + sl * 32)
                                                        : make_float4(0.f, 0.f, 0.f, 0.f);
    }

    // prefetch B fragments for cks = 0
    uint4 bf[2][4];
#pragma unroll
    for (int g = 0; g < 4; g++) bf[0][g] = bq[g * 32];

    // A-ldsm lane addressing (constant across ks)
    const uint32_t arow = (uint32_t)(lane & 15);
    const uint32_t acolb = (uint32_t)(((lane >> 4) << 3) * 2);   // byte offset of 8-col group

    for (int c = 0; c < NCHUNK; c++) {
        const int s = c & 1;

        // STS A(c): round to fp16, single plane
#pragma unroll
        for (int sl = 0; sl < 2; sl++) {
            __half h0 = __float2half_rn(xv[sl].x), h1 = __float2half_rn(xv[sl].y);
            __half h2 = __float2half_rn(xv[sl].z), h3 = __float2half_rn(xv[sl].w);
            uint2 ph = make_uint2((uint32_t)*(uint16_t*)&h0 | ((uint32_t)*(uint16_t*)&h1 << 16),
                                  (uint32_t)*(uint16_t*)&h2 | ((uint32_t)*(uint16_t*)&h3 << 16));
            uint32_t off = (uint32_t)(xrow * A_ROWB + xf4 * 8 + sl * 64);
            *(uint2*)(smem + OFF_A + s * A_STAGE + off) = ph;
        }
        __syncthreads();

        // issue next chunk's x loads (latency hidden under this chunk's compute)
        if (c + 1 < NCHUNK) {
#pragma unroll
            for (int sl = 0; sl < 2; sl++) {
                int k0 = (c + 1) * 64 + xf4 * 4 + sl * 32;
                xv[sl] = (LVALID % 64 == 0 || k0 + 4 <= LVALID)
                             ? *(const float4*)(px + (c + 1) * 64 + sl * 32)
                             : make_float4(0.f, 0.f, 0.f, 0.f);
            }
        }

        // ---- compute: ks loop with A-ldsm and B-LDG both pipelined 1 ks ahead ----
        const uint32_t aB = sb + OFF_A + s * A_STAGE;

        uint32_t ah[2][2][4];   // [buffer][mt][4]
#pragma unroll
        for (int mt = 0; mt < 2; mt++) {
            uint32_t aoff = (arow + mt * 16) * A_ROWB + acolb;
            LDSM_X4(ah[0][mt][0], ah[0][mt][1], ah[0][mt][2], ah[0][mt][3], aB + aoff);
        }

#pragma unroll
        for (int ks = 0; ks < 4; ks++) {
            const int cb = ks & 1, nb = cb ^ 1;
            const int ncks = (ks < 3) ? (c * 4 + ks + 1) : ((c + 1) * 4);
            if (ks < 3 || c + 1 < NCHUNK) {
#pragma unroll
                for (int g = 0; g < 4; g++) bf[nb][g] = bq[(size_t)ncks * 1024 + g * 32];
            }
            if (ks < 3) {
#pragma unroll
                for (int mt = 0; mt < 2; mt++) {
                    uint32_t aoff = (arow + mt * 16) * A_ROWB + acolb + (uint32_t)(ks + 1) * 32;
                    LDSM_X4(ah[nb][mt][0], ah[nb][mt][1], ah[nb][mt][2], ah[nb][mt][3], aB + aoff);
                }
            }
#pragma unroll
            for (int g = 0; g < 4; g++) {
                MMA16816(acc[0][2 * g],     ah[cb][0][0], ah[cb][0][1], ah[cb][0][2], ah[cb][0][3], bf[cb][g].x, bf[cb][g].y);
                MMA16816(acc[0][2 * g + 1], ah[cb][0][0], ah[cb][0][1], ah[cb][0][2], ah[cb][0][3], bf[cb][g].z, bf[cb][g].w);
                MMA16816(acc[1][2 * g],     ah[cb][1][0], ah[cb][1][1], ah[cb][1][2], ah[cb][1][3], bf[cb][g].x, bf[cb][g].y);
                MMA16816(acc[1][2 * g + 1], ah[cb][1][0], ah[cb][1][1], ah[cb][1][2], ah[cb][1][3], bf[cb][g].z, bf[cb][g].w);
            }
        }
    }

    // ================= epilogue: bias + ReLU + LN =================
    float* ssum = (float*)(smem + OFF_SSUM);
    float* sssq = (float*)(smem + OFF_SSSQ);
    float* rst  = (float*)(smem + OFF_RST);

#pragma unroll
    for (int mt = 0; mt < 2; mt++) {
        float sum0 = 0.f, ssq0 = 0.f, sum1 = 0.f, ssq1 = 0.f;
#pragma unroll
        for (int t = 0; t < 8; t++) {
            int cb = wn * 64 + t * 8 + (lane & 3) * 2;
            float b0v = bias_s[cb], b1v = bias_s[cb + 1];
            float h;
            h = fmaxf(acc[mt][t][0] + b0v, 0.f); acc[mt][t][0] = h; sum0 += h; ssq0 += h * h;
            h = fmaxf(acc[mt][t][1] + b1v, 0.f); acc[mt][t][1] = h; sum0 += h; ssq0 += h * h;
            h = fmaxf(acc[mt][t][2] + b0v, 0.f); acc[mt][t][2] = h; sum1 += h; ssq1 += h * h;
            h = fmaxf(acc[mt][t][3] + b1v, 0.f); acc[mt][t][3] = h; sum1 += h; ssq1 += h * h;
        }
#pragma unroll
        for (int o = 1; o <= 2; o <<= 1) {
            sum0 += __shfl_xor_sync(0xffffffffu, sum0, o);
            ssq0 += __shfl_xor_sync(0xffffffffu, ssq0, o);
            sum1 += __shfl_xor_sync(0xffffffffu, sum1, o);
            ssq1 += __shfl_xor_sync(0xffffffffu, ssq1, o);
        }
        if ((lane & 3) == 0) {
            int r0 = mt * 16 + (lane >> 2);
            ssum[r0 * 8 + wn] = sum0;       sssq[r0 * 8 + wn] = ssq0;
            ssum[(r0 + 8) * 8 + wn] = sum1; sssq[(r0 + 8) * 8 + wn] = ssq1;
        }
    }
    __syncthreads();
    if (tid < 32) {
        float s = 0.f, q = 0.f;
#pragma unroll
        for (int i = 0; i < 8; i++) { s += ssum[tid * 8 + i]; q += sssq[tid * 8 + i]; }
        float mean = s * (1.f / 512.f);
        float var  = q * (1.f / 512.f) - mean * mean;
        rst[tid * 2] = mean;
        rst[tid * 2 + 1] = rsqrtf(var + 1e-5f);
    }
    __syncthreads();

    // staged, coalesced stores: per mt-half, STS scattered -> LDS/STG coalesced
    float* stg = (float*)(smem + OFF_STG);
#pragma unroll
    for (int mt = 0; mt < 2; mt++) {
        {
            int r0 = mt * 16 + (lane >> 2);                 // rows r0 (v0) and r0+8 (v1)
            float m0 = rst[r0 * 2], rs0 = rst[r0 * 2 + 1];
            float m1 = rst[(r0 + 8) * 2], rs1 = rst[(r0 + 8) * 2 + 1];
            int sr0 = lane >> 2;                            // staging rows 0..7 / 8..15
#pragma unroll
            for (int t = 0; t < 8; t++) {
                int cb = wn * 64 + t * 8 + (lane & 3) * 2;
                float g0 = gam_s[cb], g1 = gam_s[cb + 1];
                float e0 = bet_s[cb], e1 = bet_s[cb + 1];
                float2 v0 = make_float2((acc[mt][t][0] - m0) * rs0 * g0 + e0,
                                        (acc[mt][t][1] - m0) * rs0 * g1 + e1);
                float2 v1 = make_float2((acc[mt][t][2] - m1) * rs1 * g0 + e0,
                                        (acc[mt][t][3] - m1) * rs1 * g1 + e1);
                *(float2*)(stg + sr0 * STG_PITCH + cb) = v0;
                *(float2*)(stg + (sr0 + 8) * STG_PITCH + cb) = v1;
            }
        }
        __syncthreads();
        {
            int sr = 2 * wn + (lane >> 4);                  // staging row 0..15
            int grow = row0 + mt * 16 + sr;
            int bb = grow / KSPLIT, jj = grow - bb * KSPLIT;
            float* orow = out + ((size_t)bb * NQ + QOFF + jj) * 512;
            const float* src = stg + sr * STG_PITCH;
            const int cl = (lane & 15) * 4;
#pragma unroll
            for (int qi = 0; qi < 8; qi++) {
                float4 v = *(const float4*)(src + cl + qi * 64);
                *(float4*)(orow + cl + qi * 64) = v;
            }
        }
        __syncthreads();
    }
}

__global__ void __launch_bounds__(THREADS, 2)
fused_kernel(const float* __restrict__ x,
             const float* b0, const float* g0, const float* be0,
             const float* b1, const float* g1, const float* be1,
             const float* b2, const float* g2, const float* be2,
             float* __restrict__ out) {
    const int blk = blockIdx.x;
    if (blk < 64)         run_split<1,  400, 7, 0,     0 >(x, b0, g0, be0, out, g_w0, blk);
    else if (blk < 3904)  run_split<60, 256, 4, 400,   1 >(x, b1, g1, be1, out, g_w1, blk - 64);
    else                  run_split<36, 256, 4, 15760, 61>(x, b2, g2, be2, out, g_w2, blk - 3904);
}

// ================= weight prep: W f32 -> fp16 MMA-fragment layout =================
__device__ __forceinline__ uint32_t rdh(const float* __restrict__ W, int Lvalid, int k, int n) {
    float v = (k < Lvalid) ? W[(size_t)k * 512 + n] : 0.f;
    __half h = __float2half_rn(v);
    return (uint32_t)*(uint16_t*)&h;
}
__device__ __forceinline__ void prep_frag(const float* __restrict__ W, uint4* dst,
                                          int Lvalid, int t) {
    int lane = t & 31;
    int j    = (t >> 5) & 31;       // n16-group
    int cks  = t >> 10;             // c*4 + ks
    int k0   = cks * 16 + (lane & 3) * 2;
    int nv   = j * 16 + (lane >> 2);
    uint4 o;
    o.x = rdh(W, Lvalid, k0,     nv)     | (rdh(W, Lvalid, k0 + 1, nv)     << 16);
    o.y = rdh(W, Lvalid, k0 + 8, nv)     | (rdh(W, Lvalid, k0 + 9, nv)     << 16);
    o.z = rdh(W, Lvalid, k0,     nv + 8) | (rdh(W, Lvalid, k0 + 1, nv + 8) << 16);
    o.w = rdh(W, Lvalid, k0 + 8, nv + 8) | (rdh(W, Lvalid, k0 + 9, nv + 8) << 16);
    dst[t] = o;
}

__global__ void prep_kernel(const float* __restrict__ W0, const float* __restrict__ W1,
                            const float* __restrict__ W2) {
    const int idx = blockIdx.x * blockDim.x + threadIdx.x;
    const int T0 = 448 * 512 / 8, T1 = 256 * 512 / 8, T2 = 256 * 512 / 8;
    if (idx < T0)                prep_frag(W0, g_w0, 400, idx);
    else if (idx < T0 + T1)      prep_frag(W1, g_w1, 256, idx - T0);
    else if (idx < T0 + T1 + T2) prep_frag(W2, g_w2, 256, idx - T0 - T1);
}

// ================= launch =================
extern "C" void kernel_launch(void* const* d_in, const int* in_sizes, int n_in,
                              void* d_out, int out_size) {
    (void)in_sizes; (void)n_in; (void)out_size;
    const float* x = (const float*)d_in[0];
    float* out = (float*)d_out;

    cudaFuncSetAttribute(fused_kernel, cudaFuncAttributeMaxDynamicSharedMemorySize, SMEM_TOTAL);

    const int prep_total = (448 + 256 + 256) * 512 / 8;
    prep_kernel<<<(prep_total + 255) / 256, 256>>>(
        (const float*)d_in[1], (const float*)d_in[5], (const float*)d_in[9]);

    fused_kernel<<<6208, THREADS, SMEM_TOTAL>>>(
        x,
        (const float*)d_in[2],  (const float*)d_in[3],  (const float*)d_in[4],
        (const float*)d_in[6],  (const float*)d_in[7],  (const float*)d_in[8],
        (const float*)d_in[10], (const float*)d_in[11], (const float*)d_in[12],
        out);
}

// round 14
// speedup vs baseline: 1.0393x; 1.0393x over previous
#include <cuda_runtime.h>
#include <cuda_fp16.h>
#include <cstdint>

#define TOTAL_DIM 24976
#define NQ        97
#define THREADS   256

// ---- dynamic SMEM layout (bytes) ----
#define OFF_BIAS  0
#define OFF_GAMMA 2048
#define OFF_BETA  4096
#define OFF_SSUM  6144     // [32][8] f32
#define OFF_SSSQ  7168     // [32][8] f32
#define OFF_A     8192     // 2 stages x 32 rows x 144B (single fp16 plane)
#define A_STAGE   4608
#define A_ROWB    144
#define SMEM_TOTAL 17408

// ---- prepped weights in MMA FRAGMENT layout ----
// uint4 index: cks*1024 + j*32 + lane   (cks = c*4+ks, j = n16-group 0..31)
__device__ uint4 g_w0[448 * 512 / 8];
__device__ uint4 g_w1[256 * 512 / 8];
__device__ uint4 g_w2[256 * 512 / 8];

__device__ __forceinline__ uint32_t smem_u32(const void* p) {
    uint32_t a;
    asm("{ .reg .u64 t; cvta.to.shared.u64 t, %1; cvt.u32.u64 %0, t; }" : "=r"(a) : "l"(p));
    return a;
}
#define LDSM_X4(r0, r1, r2, r3, a) \
    asm volatile("ldmatrix.sync.aligned.m8n8.x4.shared.b16 {%0,%1,%2,%3}, [%4];" \
                 : "=r"(r0), "=r"(r1), "=r"(r2), "=r"(r3) : "r"(a))
#define MMA16816(c, a0, a1, a2, a3, b0, b1) \
    asm volatile("mma.sync.aligned.m16n8k16.row.col.f32.f16.f16.f32 " \
                 "{%0,%1,%2,%3}, {%4,%5,%6,%7}, {%8,%9}, {%0,%1,%2,%3};" \
                 : "+f"((c)[0]), "+f"((c)[1]), "+f"((c)[2]), "+f"((c)[3]) \
                 : "r"(a0), "r"(a1), "r"(a2), "r"(a3), "r"(b0), "r"(b1))

// ================= fused GEMM + bias + ReLU + LayerNorm =================
// CTA: 32 rows x 512 cols, 8 warps, warp tile 32 x 64 (wn = wid). BK = 64.
// 2 CTAs/SM; B fragments stream from global (L1/L2-hot), A via smem.
// A-ldsm and B-LDG software-pipelined one ks ahead. One-barrier epilogue.
template <int KSPLIT, int LVALID, int NCHUNK, int SEGOFF, int QOFF>
__device__ __forceinline__ void run_split(const float* __restrict__ x,
                                          const float* __restrict__ bias_g,
                                          const float* __restrict__ gamma_g,
                                          const float* __restrict__ beta_g,
                                          float* __restrict__ out,
                                          const uint4* __restrict__ wfrag,
                                          int tile) {
    extern __shared__ char smem[];
    const uint32_t sb = smem_u32(smem);
    const int tid = threadIdx.x, lane = tid & 31, wn = tid >> 5;
    const int row0 = tile * 32;

    float* bias_s = (float*)(smem + OFF_BIAS);
    float* gam_s  = (float*)(smem + OFF_GAMMA);
    float* bet_s  = (float*)(smem + OFF_BETA);
    for (int i = tid; i < 512; i += THREADS) {
        bias_s[i] = bias_g[i]; gam_s[i] = gamma_g[i]; bet_s[i] = beta_g[i];
    }

    // per-thread x mapping: one row (tid>>3, 0..31), two float4 slots (tid&7, +32 halfs)
    const int xrow = tid >> 3, xf4 = tid & 7;
    const float* px;
    {
        int gr = row0 + xrow;
        int bb = gr / KSPLIT, jj = gr - bb * KSPLIT;
        px = x + (size_t)bb * TOTAL_DIM + SEGOFF + (size_t)jj * LVALID + xf4 * 4;
    }

    float acc[2][8][4];
#pragma unroll
    for (int mt = 0; mt < 2; mt++)
#pragma unroll
        for (int t = 0; t < 8; t++)
#pragma unroll
            for (int c = 0; c < 4; c++) acc[mt][t][c] = 0.f;

    // B fragment base pointer for this warp/lane
    const uint4* bq = wfrag + (size_t)(wn * 4) * 32 + lane;

    float4 xv[2];
#pragma unroll
    for (int sl = 0; sl < 2; sl++) {
        int k0 = xf4 * 4 + sl * 32;
        xv[sl] = (LVALID % 64 == 0 || k0 + 4 <= LVALID) ? *(const float4*)(px + sl * 32)
                                                        : make_float4(0.f, 0.f, 0.f, 0.f);
    }

    // prefetch B fragments for cks = 0
    uint4 bf[2][4];
#pragma unroll
    for (int g = 0; g < 4; g++) bf[0][g] = bq[g * 32];

    // A-ldsm lane addressing (constant across ks)
    const uint32_t arow = (uint32_t)(lane & 15);
    const uint32_t acolb = (uint32_t)(((lane >> 4) << 3) * 2);   // byte offset of 8-col group

    for (int c = 0; c < NCHUNK; c++) {
        const int s = c & 1;

        // STS A(c): round to fp16, single plane
#pragma unroll
        for (int sl = 0; sl < 2; sl++) {
            __half h0 = __float2half_rn(xv[sl].x), h1 = __float2half_rn(xv[sl].y);
            __half h2 = __float2half_rn(xv[sl].z), h3 = __float2half_rn(xv[sl].w);
            uint2 ph = make_uint2((uint32_t)*(uint16_t*)&h0 | ((uint32_t)*(uint16_t*)&h1 << 16),
                                  (uint32_t)*(uint16_t*)&h2 | ((uint32_t)*(uint16_t*)&h3 << 16));
            uint32_t off = (uint32_t)(xrow * A_ROWB + xf4 * 8 + sl * 64);
            *(uint2*)(smem + OFF_A + s * A_STAGE + off) = ph;
        }
        __syncthreads();

        // issue next chunk's x loads (latency hidden under this chunk's compute)
        if (c + 1 < NCHUNK) {
#pragma unroll
            for (int sl = 0; sl < 2; sl++) {
                int k0 = (c + 1) * 64 + xf4 * 4 + sl * 32;
                xv[sl] = (LVALID % 64 == 0 || k0 + 4 <= LVALID)
                             ? *(const float4*)(px + (c + 1) * 64 + sl * 32)
                             : make_float4(0.f, 0.f, 0.f, 0.f);
            }
        }

        // ---- compute: ks loop with A-ldsm and B-LDG both pipelined 1 ks ahead ----
        const uint32_t aB = sb + OFF_A + s * A_STAGE;

        uint32_t ah[2][2][4];   // [buffer][mt][4]
#pragma unroll
        for (int mt = 0; mt < 2; mt++) {
            uint32_t aoff = (arow + mt * 16) * A_ROWB + acolb;
            LDSM_X4(ah[0][mt][0], ah[0][mt][1], ah[0][mt][2], ah[0][mt][3], aB + aoff);
        }

#pragma unroll
        for (int ks = 0; ks < 4; ks++) {
            const int cb = ks & 1, nb = cb ^ 1;
            const int ncks = (ks < 3) ? (c * 4 + ks + 1) : ((c + 1) * 4);
            if (ks < 3 || c + 1 < NCHUNK) {
#pragma unroll
                for (int g = 0; g < 4; g++) bf[nb][g] = bq[(size_t)ncks * 1024 + g * 32];
            }
            if (ks < 3) {
#pragma unroll
                for (int mt = 0; mt < 2; mt++) {
                    uint32_t aoff = (arow + mt * 16) * A_ROWB + acolb + (uint32_t)(ks + 1) * 32;
                    LDSM_X4(ah[nb][mt][0], ah[nb][mt][1], ah[nb][mt][2], ah[nb][mt][3], aB + aoff);
                }
            }
#pragma unroll
            for (int g = 0; g < 4; g++) {
                MMA16816(acc[0][2 * g],     ah[cb][0][0], ah[cb][0][1], ah[cb][0][2], ah[cb][0][3], bf[cb][g].x, bf[cb][g].y);
                MMA16816(acc[0][2 * g + 1], ah[cb][0][0], ah[cb][0][1], ah[cb][0][2], ah[cb][0][3], bf[cb][g].z, bf[cb][g].w);
                MMA16816(acc[1][2 * g],     ah[cb][1][0], ah[cb][1][1], ah[cb][1][2], ah[cb][1][3], bf[cb][g].x, bf[cb][g].y);
                MMA16816(acc[1][2 * g + 1], ah[cb][1][0], ah[cb][1][1], ah[cb][1][2], ah[cb][1][3], bf[cb][g].z, bf[cb][g].w);
            }
        }
    }

    // ================= epilogue: bias + ReLU + LN (single barrier) =================
    float* ssum = (float*)(smem + OFF_SSUM);
    float* sssq = (float*)(smem + OFF_SSSQ);

#pragma unroll
    for (int mt = 0; mt < 2; mt++) {
        float sum0 = 0.f, ssq0 = 0.f, sum1 = 0.f, ssq1 = 0.f;
#pragma unroll
        for (int t = 0; t < 8; t++) {
            int cb = wn * 64 + t * 8 + (lane & 3) * 2;
            float b0v = bias_s[cb], b1v = bias_s[cb + 1];
            float h;
            h = fmaxf(acc[mt][t][0] + b0v, 0.f); acc[mt][t][0] = h; sum0 += h; ssq0 += h * h;
            h = fmaxf(acc[mt][t][1] + b1v, 0.f); acc[mt][t][1] = h; sum0 += h; ssq0 += h * h;
            h = fmaxf(acc[mt][t][2] + b0v, 0.f); acc[mt][t][2] = h; sum1 += h; ssq1 += h * h;
            h = fmaxf(acc[mt][t][3] + b1v, 0.f); acc[mt][t][3] = h; sum1 += h; ssq1 += h * h;
        }
#pragma unroll
        for (int o = 1; o <= 2; o <<= 1) {
            sum0 += __shfl_xor_sync(0xffffffffu, sum0, o);
            ssq0 += __shfl_xor_sync(0xffffffffu, ssq0, o);
            sum1 += __shfl_xor_sync(0xffffffffu, sum1, o);
            ssq1 += __shfl_xor_sync(0xffffffffu, ssq1, o);
        }
        if ((lane & 3) == 0) {
            int r0 = mt * 16 + (lane >> 2);
            ssum[r0 * 8 + wn] = sum0;       sssq[r0 * 8 + wn] = ssq0;
            ssum[(r0 + 8) * 8 + wn] = sum1; sssq[(r0 + 8) * 8 + wn] = ssq1;
        }
    }
    __syncthreads();   // the only epilogue barrier

    // each warp redundantly reduces the 8 partials for its own rows (broadcast LDS)
#pragma unroll
    for (int mt = 0; mt < 2; mt++) {
        int r0 = mt * 16 + (lane >> 2);
        float4 p0a = *(const float4*)(ssum + r0 * 8), p0b = *(const float4*)(ssum + r0 * 8 + 4);
        float4 q0a = *(const float4*)(sssq + r0 * 8), q0b = *(const float4*)(sssq + r0 * 8 + 4);
        float4 p1a = *(const float4*)(ssum + (r0 + 8) * 8), p1b = *(const float4*)(ssum + (r0 + 8) * 8 + 4);
        float4 q1a = *(const float4*)(sssq + (r0 + 8) * 8), q1b = *(const float4*)(sssq + (r0 + 8) * 8 + 4);
        float s0 = ((p0a.x + p0a.y) + (p0a.z + p0a.w)) + ((p0b.x + p0b.y) + (p0b.z + p0b.w));
        float q0 = ((q0a.x + q0a.y) + (q0a.z + q0a.w)) + ((q0b.x + q0b.y) + (q0b.z + q0b.w));
        float s1 = ((p1a.x + p1a.y) + (p1a.z + p1a.w)) + ((p1b.x + p1b.y) + (p1b.z + p1b.w));
        float q1 = ((q1a.x + q1a.y) + (q1a.z + q1a.w)) + ((q1b.x + q1b.y) + (q1b.z + q1b.w));
        float m0  = s0 * (1.f / 512.f);
        float rs0 = rsqrtf(q0 * (1.f / 512.f) - m0 * m0 + 1e-5f);
        float m1  = s1 * (1.f / 512.f);
        float rs1 = rsqrtf(q1 * (1.f / 512.f) - m1 * m1 + 1e-5f);

        int gr0 = row0 + r0, gr1 = gr0 + 8;
        int b0i = gr0 / KSPLIT, j0 = gr0 - b0i * KSPLIT;
        int b1i = gr1 / KSPLIT, j1 = gr1 - b1i * KSPLIT;
        float* o0 = out + ((size_t)b0i * NQ + QOFF + j0) * 512;
        float* o1 = out + ((size_t)b1i * NQ + QOFF + j1) * 512;
#pragma unroll
        for (int t = 0; t < 8; t++) {
            int cb = wn * 64 + t * 8 + (lane & 3) * 2;
            float g0 = gam_s[cb], g1 = gam_s[cb + 1];
            float e0 = bet_s[cb], e1 = bet_s[cb + 1];
            float2 v0 = make_float2((acc[mt][t][0] - m0) * rs0 * g0 + e0,
                                    (acc[mt][t][1] - m0) * rs0 * g1 + e1);
            float2 v1 = make_float2((acc[mt][t][2] - m1) * rs1 * g0 + e0,
                                    (acc[mt][t][3] - m1) * rs1 * g1 + e1);
            __stcs((float2*)(o0 + cb), v0);
            __stcs((float2*)(o1 + cb), v1);
        }
    }
}

__global__ void __launch_bounds__(THREADS, 2)
fused_kernel(const float* __restrict__ x,
             const float* b0, const float* g0, const float* be0,
             const float* b1, const float* g1, const float* be1,
             const float* b2, const float* g2, const float* be2,
             float* __restrict__ out) {
    const int blk = blockIdx.x;
    if (blk < 64)         run_split<1,  400, 7, 0,     0 >(x, b0, g0, be0, out, g_w0, blk);
    else if (blk < 3904)  run_split<60, 256, 4, 400,   1 >(x, b1, g1, be1, out, g_w1, blk - 64);
    else                  run_split<36, 256, 4, 15760, 61>(x, b2, g2, be2, out, g_w2, blk - 3904);
}

// ================= weight prep: W f32 -> fp16 MMA-fragment layout =================
__device__ __forceinline__ uint32_t rdh(const float* __restrict__ W, int Lvalid, int k, int n) {
    float v = (k < Lvalid) ? W[(size_t)k * 512 + n] : 0.f;
    __half h = __float2half_rn(v);
    return (uint32_t)*(uint16_t*)&h;
}
__device__ __forceinline__ void prep_frag(const float* __restrict__ W, uint4* dst,
                                          int Lvalid, int t) {
    int lane = t & 31;
    int j    = (t >> 5) & 31;       // n16-group
    int cks  = t >> 10;             // c*4 + ks
    int k0   = cks * 16 + (lane & 3) * 2;
    int nv   = j * 16 + (lane >> 2);
    uint4 o;
    o.x = rdh(W, Lvalid, k0,     nv)     | (rdh(W, Lvalid, k0 + 1, nv)     << 16);
    o.y = rdh(W, Lvalid, k0 + 8, nv)     | (rdh(W, Lvalid, k0 + 9, nv)     << 16);
    o.z = rdh(W, Lvalid, k0,     nv + 8) | (rdh(W, Lvalid, k0 + 1, nv + 8) << 16);
    o.w = rdh(W, Lvalid, k0 + 8, nv + 8) | (rdh(W, Lvalid, k0 + 9, nv + 8) << 16);
    dst[t] = o;
}

__global__ void prep_kernel(const float* __restrict__ W0, const float* __restrict__ W1,
                            const float* __restrict__ W2) {
    const int idx = blockIdx.x * blockDim.x + threadIdx.x;
    const int T0 = 448 * 512 / 8, T1 = 256 * 512 / 8, T2 = 256 * 512 / 8;
    if (idx < T0)                prep_frag(W0, g_w0, 400, idx);
    else if (idx < T0 + T1)      prep_frag(W1, g_w1, 256, idx - T0);
    else if (idx < T0 + T1 + T2) prep_frag(W2, g_w2, 256, idx - T0 - T1);
}

// ================= launch =================
extern "C" void kernel_launch(void* const* d_in, const int* in_sizes, int n_in,
                              void* d_out, int out_size) {
    (void)in_sizes; (void)n_in; (void)out_size;
    const float* x = (const float*)d_in[0];
    float* out = (float*)d_out;

    cudaFuncSetAttribute(fused_kernel, cudaFuncAttributeMaxDynamicSharedMemorySize, SMEM_TOTAL);

    const int prep_total = (448 + 256 + 256) * 512 / 8;
    prep_kernel<<<(prep_total + 255) / 256, 256>>>(
        (const float*)d_in[1], (const float*)d_in[5], (const float*)d_in[9]);

    fused_kernel<<<6208, THREADS, SMEM_TOTAL>>>(
        x,
        (const float*)d_in[2],  (const float*)d_in[3],  (const float*)d_in[4],
        (const float*)d_in[6],  (const float*)d_in[7],  (const float*)d_in[8],
        (const float*)d_in[10], (const float*)d_in[11], (const float*)d_in[12],
        out);
}

// round 15
// speedup vs baseline: 1.0973x; 1.0558x over previous
#include <cuda_runtime.h>
#include <cuda_fp16.h>
#include <cstdint>

#define TOTAL_DIM 24976
#define NQ        97
#define THREADS   256

// ---- dynamic SMEM layout (bytes) ----
#define OFF_BIAS  0
#define OFF_GAMMA 2048
#define OFF_BETA  4096
#define OFF_SSUM  6144     // [32][8] f32
#define OFF_SSSQ  7168     // [32][8] f32
#define OFF_A     8192     // NCHUNK blocks x (32 rows x 144B), fp16 A, whole K upfront
#define A_CHUNK   4608
#define A_ROWB    144
#define SMEM_TOTAL (8192 + 7 * 4608)   // sized for the largest split (NCHUNK=7)

// ---- prepped weights in MMA FRAGMENT layout ----
// uint4 index: cks*1024 + j*32 + lane   (cks = k16-step, j = n16-group 0..31)
__device__ uint4 g_w0[448 * 512 / 8];
__device__ uint4 g_w1[256 * 512 / 8];
__device__ uint4 g_w2[256 * 512 / 8];

__device__ __forceinline__ uint32_t smem_u32(const void* p) {
    uint32_t a;
    asm("{ .reg .u64 t; cvta.to.shared.u64 t, %1; cvt.u32.u64 %0, t; }" : "=r"(a) : "l"(p));
    return a;
}
#define LDSM_X4(r0, r1, r2, r3, a) \
    asm volatile("ldmatrix.sync.aligned.m8n8.x4.shared.b16 {%0,%1,%2,%3}, [%4];" \
                 : "=r"(r0), "=r"(r1), "=r"(r2), "=r"(r3) : "r"(a))
#define MMA16816(c, a0, a1, a2, a3, b0, b1) \
    asm volatile("mma.sync.aligned.m16n8k16.row.col.f32.f16.f16.f32 " \
                 "{%0,%1,%2,%3}, {%4,%5,%6,%7}, {%8,%9}, {%0,%1,%2,%3};" \
                 : "+f"((c)[0]), "+f"((c)[1]), "+f"((c)[2]), "+f"((c)[3]) \
                 : "r"(a0), "r"(a1), "r"(a2), "r"(a3), "r"(b0), "r"(b1))

// ================= fused GEMM + bias + ReLU + LayerNorm =================
// CTA: 32 rows x 512 cols, 8 warps, warp tile 32 x 64 (wn = wid).
// 2 CTAs/SM. Whole A tile staged to smem in the prologue (ONE barrier),
// then a fully barrier-free mainloop: warps drift independently across K.
// B fragments stream from global (L1/L2-hot); A-ldsm and B-LDG pipelined
// one k16-step ahead. Single-barrier epilogue.
template <int KSPLIT, int LVALID, int NCHUNK, int SEGOFF, int QOFF>
__device__ __forceinline__ void run_split(const float* __restrict__ x,
                                          const float* __restrict__ bias_g,
                                          const float* __restrict__ gamma_g,
                                          const float* __restrict__ beta_g,
                                          float* __restrict__ out,
                                          const uint4* __restrict__ wfrag,
                                          int tile) {
    constexpr int NSLOT = 2 * NCHUNK;   // 32-half slots of A per row
    constexpr int NK    = 4 * NCHUNK;   // k16 steps

    extern __shared__ char smem[];
    const uint32_t sb = smem_u32(smem);
    const int tid = threadIdx.x, lane = tid & 31, wn = tid >> 5;
    const int row0 = tile * 32;

    float* bias_s = (float*)(smem + OFF_BIAS);
    float* gam_s  = (float*)(smem + OFF_GAMMA);
    float* bet_s  = (float*)(smem + OFF_BETA);
    for (int i = tid; i < 512; i += THREADS) {
        bias_s[i] = bias_g[i]; gam_s[i] = gamma_g[i]; bet_s[i] = beta_g[i];
    }

    // per-thread x mapping: one row (tid>>3, 0..31), slot = 32-half column group
    const int xrow = tid >> 3, xf4 = tid & 7;
    const float* px;
    {
        int gr = row0 + xrow;
        int bb = gr / KSPLIT, jj = gr - bb * KSPLIT;
        px = x + (size_t)bb * TOTAL_DIM + SEGOFF + (size_t)jj * LVALID + xf4 * 4;
    }

    // ---- prologue: load + convert + store the ENTIRE A tile, then one barrier ----
#pragma unroll
    for (int s0 = 0; s0 < NSLOT; s0 += 4) {
        float4 xb[4];
#pragma unroll
        for (int i = 0; i < 4; i++) {
            if (s0 + i < NSLOT) {
                int k0 = (s0 + i) * 32 + xf4 * 4;
                xb[i] = (LVALID % 64 == 0 || k0 + 4 <= LVALID)
                            ? *(const float4*)(px + (s0 + i) * 32)
                            : make_float4(0.f, 0.f, 0.f, 0.f);
            }
        }
#pragma unroll
        for (int i = 0; i < 4; i++) {
            if (s0 + i < NSLOT) {
                __half h0 = __float2half_rn(xb[i].x), h1 = __float2half_rn(xb[i].y);
                __half h2 = __float2half_rn(xb[i].z), h3 = __float2half_rn(xb[i].w);
                uint2 ph = make_uint2(
                    (uint32_t)*(uint16_t*)&h0 | ((uint32_t)*(uint16_t*)&h1 << 16),
                    (uint32_t)*(uint16_t*)&h2 | ((uint32_t)*(uint16_t*)&h3 << 16));
                uint32_t off = (uint32_t)(OFF_A + ((s0 + i) >> 1) * A_CHUNK
                                          + xrow * A_ROWB + ((s0 + i) & 1) * 64 + xf4 * 8);
                *(uint2*)(smem + off) = ph;
            }
        }
    }
    __syncthreads();   // the ONLY pre-epilogue barrier

    float acc[2][8][4];
#pragma unroll
    for (int mt = 0; mt < 2; mt++)
#pragma unroll
        for (int t = 0; t < 8; t++)
#pragma unroll
            for (int c = 0; c < 4; c++) acc[mt][t][c] = 0.f;

    // B fragment base pointer for this warp/lane
    const uint4* bq = wfrag + (size_t)(wn * 4) * 32 + lane;

    // A-ldsm lane addressing
    const uint32_t arow  = (uint32_t)(lane & 15);
    const uint32_t acolb = (uint32_t)(((lane >> 4) << 3) * 2);

    // prime pipelines for cks = 0
    uint4 bf[2][4];
#pragma unroll
    for (int g = 0; g < 4; g++) bf[0][g] = bq[g * 32];

    uint32_t ah[2][2][4];
#pragma unroll
    for (int mt = 0; mt < 2; mt++) {
        uint32_t aoff = sb + (uint32_t)(OFF_A) + (arow + mt * 16) * A_ROWB + acolb;
        LDSM_X4(ah[0][mt][0], ah[0][mt][1], ah[0][mt][2], ah[0][mt][3], aoff);
    }

    // ---- barrier-free mainloop over all k16 steps ----
#pragma unroll 4
    for (int cks = 0; cks < NK; cks++) {
        const int cb = cks & 1, nb = cb ^ 1;
        if (cks + 1 < NK) {
#pragma unroll
            for (int g = 0; g < 4; g++) bf[nb][g] = bq[(size_t)(cks + 1) * 1024 + g * 32];
#pragma unroll
            for (int mt = 0; mt < 2; mt++) {
                uint32_t aoff = sb + (uint32_t)(OFF_A + ((cks + 1) >> 2) * A_CHUNK
                                                + ((cks + 1) & 3) * 32)
                                + (arow + mt * 16) * A_ROWB + acolb;
                LDSM_X4(ah[nb][mt][0], ah[nb][mt][1], ah[nb][mt][2], ah[nb][mt][3], aoff);
            }
        }
#pragma unroll
        for (int g = 0; g < 4; g++) {
            MMA16816(acc[0][2 * g],     ah[cb][0][0], ah[cb][0][1], ah[cb][0][2], ah[cb][0][3], bf[cb][g].x, bf[cb][g].y);
            MMA16816(acc[0][2 * g + 1], ah[cb][0][0], ah[cb][0][1], ah[cb][0][2], ah[cb][0][3], bf[cb][g].z, bf[cb][g].w);
            MMA16816(acc[1][2 * g],     ah[cb][1][0], ah[cb][1][1], ah[cb][1][2], ah[cb][1][3], bf[cb][g].x, bf[cb][g].y);
            MMA16816(acc[1][2 * g + 1], ah[cb][1][0], ah[cb][1][1], ah[cb][1][2], ah[cb][1][3], bf[cb][g].z, bf[cb][g].w);
        }
    }

    // ================= epilogue: bias + ReLU + LN (single barrier) =================
    float* ssum = (float*)(smem + OFF_SSUM);
    float* sssq = (float*)(smem + OFF_SSSQ);

#pragma unroll
    for (int mt = 0; mt < 2; mt++) {
        float sum0 = 0.f, ssq0 = 0.f, sum1 = 0.f, ssq1 = 0.f;
#pragma unroll
        for (int t = 0; t < 8; t++) {
            int cb = wn * 64 + t * 8 + (lane & 3) * 2;
            float b0v = bias_s[cb], b1v = bias_s[cb + 1];
            float h;
            h = fmaxf(acc[mt][t][0] + b0v, 0.f); acc[mt][t][0] = h; sum0 += h; ssq0 += h * h;
            h = fmaxf(acc[mt][t][1] + b1v, 0.f); acc[mt][t][1] = h; sum0 += h; ssq0 += h * h;
            h = fmaxf(acc[mt][t][2] + b0v, 0.f); acc[mt][t][2] = h; sum1 += h; ssq1 += h * h;
            h = fmaxf(acc[mt][t][3] + b1v, 0.f); acc[mt][t][3] = h; sum1 += h; ssq1 += h * h;
        }
#pragma unroll
        for (int o = 1; o <= 2; o <<= 1) {
            sum0 += __shfl_xor_sync(0xffffffffu, sum0, o);
            ssq0 += __shfl_xor_sync(0xffffffffu, ssq0, o);
            sum1 += __shfl_xor_sync(0xffffffffu, sum1, o);
            ssq1 += __shfl_xor_sync(0xffffffffu, ssq1, o);
        }
        if ((lane & 3) == 0) {
            int r0 = mt * 16 + (lane >> 2);
            ssum[r0 * 8 + wn] = sum0;       sssq[r0 * 8 + wn] = ssq0;
            ssum[(r0 + 8) * 8 + wn] = sum1; sssq[(r0 + 8) * 8 + wn] = ssq1;
        }
    }
    __syncthreads();   // the only epilogue barrier

    // each warp redundantly reduces the 8 partials for its own rows (broadcast LDS)
#pragma unroll
    for (int mt = 0; mt < 2; mt++) {
        int r0 = mt * 16 + (lane >> 2);
        float4 p0a = *(const float4*)(ssum + r0 * 8), p0b = *(const float4*)(ssum + r0 * 8 + 4);
        float4 q0a = *(const float4*)(sssq + r0 * 8), q0b = *(const float4*)(sssq + r0 * 8 + 4);
        float4 p1a = *(const float4*)(ssum + (r0 + 8) * 8), p1b = *(const float4*)(ssum + (r0 + 8) * 8 + 4);
        float4 q1a = *(const float4*)(sssq + (r0 + 8) * 8), q1b = *(const float4*)(sssq + (r0 + 8) * 8 + 4);
        float s0 = ((p0a.x + p0a.y) + (p0a.z + p0a.w)) + ((p0b.x + p0b.y) + (p0b.z + p0b.w));
        float q0 = ((q0a.x + q0a.y) + (q0a.z + q0a.w)) + ((q0b.x + q0b.y) + (q0b.z + q0b.w));
        float s1 = ((p1a.x + p1a.y) + (p1a.z + p1a.w)) + ((p1b.x + p1b.y) + (p1b.z + p1b.w));
        float q1 = ((q1a.x + q1a.y) + (q1a.z + q1a.w)) + ((q1b.x + q1b.y) + (q1b.z + q1b.w));
        float m0  = s0 * (1.f / 512.f);
        float rs0 = rsqrtf(q0 * (1.f / 512.f) - m0 * m0 + 1e-5f);
        float m1  = s1 * (1.f / 512.f);
        float rs1 = rsqrtf(q1 * (1.f / 512.f) - m1 * m1 + 1e-5f);

        int gr0 = row0 + r0, gr1 = gr0 + 8;
        int b0i = gr0 / KSPLIT, j0 = gr0 - b0i * KSPLIT;
        int b1i = gr1 / KSPLIT, j1 = gr1 - b1i * KSPLIT;
        float* o0 = out + ((size_t)b0i * NQ + QOFF + j0) * 512;
        float* o1 = out + ((size_t)b1i * NQ + QOFF + j1) * 512;
#pragma unroll
        for (int t = 0; t < 8; t++) {
            int cb = wn * 64 + t * 8 + (lane & 3) * 2;
            float g0 = gam_s[cb], g1 = gam_s[cb + 1];
            float e0 = bet_s[cb], e1 = bet_s[cb + 1];
            float2 v0 = make_float2((acc[mt][t][0] - m0) * rs0 * g0 + e0,
                                    (acc[mt][t][1] - m0) * rs0 * g1 + e1);
            float2 v1 = make_float2((acc[mt][t][2] - m1) * rs1 * g0 + e0,
                                    (acc[mt][t][3] - m1) * rs1 * g1 + e1);
            __stcs((float2*)(o0 + cb), v0);
            __stcs((float2*)(o1 + cb), v1);
        }
    }
}

__global__ void __launch_bounds__(THREADS, 2)
fused_kernel(const float* __restrict__ x,
             const float* b0, const float* g0, const float* be0,
             const float* b1, const float* g1, const float* be1,
             const float* b2, const float* g2, const float* be2,
             float* __restrict__ out) {
    const int blk = blockIdx.x;
    if (blk < 64)         run_split<1,  400, 7, 0,     0 >(x, b0, g0, be0, out, g_w0, blk);
    else if (blk < 3904)  run_split<60, 256, 4, 400,   1 >(x, b1, g1, be1, out, g_w1, blk - 64);
    else                  run_split<36, 256, 4, 15760, 61>(x, b2, g2, be2, out, g_w2, blk - 3904);
}

// ================= weight prep: W f32 -> fp16 MMA-fragment layout =================
__device__ __forceinline__ uint32_t rdh(const float* __restrict__ W, int Lvalid, int k, int n) {
    float v = (k < Lvalid) ? W[(size_t)k * 512 + n] : 0.f;
    __half h = __float2half_rn(v);
    return (uint32_t)*(uint16_t*)&h;
}
__device__ __forceinline__ void prep_frag(const float* __restrict__ W, uint4* dst,
                                          int Lvalid, int t) {
    int lane = t & 31;
    int j    = (t >> 5) & 31;       // n16-group
    int cks  = t >> 10;             // k16-step
    int k0   = cks * 16 + (lane & 3) * 2;
    int nv   = j * 16 + (lane >> 2);
    uint4 o;
    o.x = rdh(W, Lvalid, k0,     nv)     | (rdh(W, Lvalid, k0 + 1, nv)     << 16);
    o.y = rdh(W, Lvalid, k0 + 8, nv)     | (rdh(W, Lvalid, k0 + 9, nv)     << 16);
    o.z = rdh(W, Lvalid, k0,     nv + 8) | (rdh(W, Lvalid, k0 + 1, nv + 8) << 16);
    o.w = rdh(W, Lvalid, k0 + 8, nv + 8) | (rdh(W, Lvalid, k0 + 9, nv + 8) << 16);
    dst[t] = o;
}

__global__ void prep_kernel(const float* __restrict__ W0, const float* __restrict__ W1,
                            const float* __restrict__ W2) {
    const int idx = blockIdx.x * blockDim.x + threadIdx.x;
    const int T0 = 448 * 512 / 8, T1 = 256 * 512 / 8, T2 = 256 * 512 / 8;
    if (idx < T0)                prep_frag(W0, g_w0, 400, idx);
    else if (idx < T0 + T1)      prep_frag(W1, g_w1, 256, idx - T0);
    else if (idx < T0 + T1 + T2) prep_frag(W2, g_w2, 256, idx - T0 - T1);
}

// ================= launch =================
extern "C" void kernel_launch(void* const* d_in, const int* in_sizes, int n_in,
                              void* d_out, int out_size) {
    (void)in_sizes; (void)n_in; (void)out_size;
    const float* x = (const float*)d_in[0];
    float* out = (float*)d_out;

    cudaFuncSetAttribute(fused_kernel, cudaFuncAttributeMaxDynamicSharedMemorySize, SMEM_TOTAL);

    const int prep_total = (448 + 256 + 256) * 512 / 8;
    prep_kernel<<<(prep_total + 255) / 256, 256>>>(
        (const float*)d_in[1], (const float*)d_in[5], (const float*)d_in[9]);

    fused_kernel<<<6208, THREADS, SMEM_TOTAL>>>(
        x,
        (const float*)d_in[2],  (const float*)d_in[3],  (const float*)d_in[4],
        (const float*)d_in[6],  (const float*)d_in[7],  (const float*)d_in[8],
        (const float*)d_in[10], (const float*)d_in[11], (const float*)d_in[12],
        out);
}